// round 13
// baseline (speedup 1.0000x reference)
#include <cuda_runtime.h>

static constexpr int SEQ_LEN = 128;
static constexpr int BATCH   = 65536;
static constexpr int PAIRS   = BATCH / 2;   // 2 columns per thread

__device__ __forceinline__ float ex2a(float x) {
    float r; asm("ex2.approx.ftz.f32 %0, %1;" : "=f"(r) : "f"(x)); return r;
}
__device__ __forceinline__ float lg2a(float x) {
    float r; asm("lg2.approx.ftz.f32 %0, %1;" : "=f"(r) : "f"(x)); return r;
}
__device__ __forceinline__ float rcpa(float x) {
    float r; asm("rcp.approx.ftz.f32 %0, %1;" : "=f"(r) : "f"(x)); return r;
}

__device__ __forceinline__ unsigned long long mk_policy() {
    unsigned long long pol;
    asm("createpolicy.fractional.L2::evict_last.b64 %0, 1.0;" : "=l"(pol));
    return pol;
}
__device__ __forceinline__ float4 ldg_el4(const float4* p, unsigned long long pol) {
    float4 v;
    asm volatile("ld.global.nc.L2::cache_hint.v4.f32 {%0,%1,%2,%3}, [%4], %5;"
                 : "=f"(v.x), "=f"(v.y), "=f"(v.z), "=f"(v.w)
                 : "l"(p), "l"(pol));
    return v;
}

struct W {
    float w6, w9, w11, w12, w13, w15, w16;
    float ew8, w10l, w14l, c_d1, c_d2;
};

// Two independent lanes, operations textually interleaved so the A and B
// MUFU chains overlap in the pipe instead of serializing.
__device__ __forceinline__ void step2(float4 x,
                                      float& sA, float& dA,
                                      float& sB, float& dB, const W& P_)
{
    float tA = x.x, rA = x.y;      float tB = x.z, rB = x.w;
    bool  suA = (rA > 1.0f);       bool  suB = (rB > 1.0f);

    float denA = fmaf(9.0f, sA, tA);   float denB = fmaf(9.0f, sB, tB);
    float rcA  = rcpa(denA);           float rcB  = rcpa(denB);
    float ceA  = suA ? P_.w10l : P_.w14l;
    float ceB  = suB ? P_.w10l : P_.w14l;
    float tcA  = tA * ceA;             float tcB  = tB * ceB;
    float EA   = ex2a(tcA * rcA);      float EB   = ex2a(tcB * rcB);

    float baA = suA ? sA : (sA + 1.0f);  float baB = suB ? sB : (sB + 1.0f);
    float kA  = suA ? -P_.w9 : P_.w13;   float kB  = suB ? -P_.w9 : P_.w13;
    float lA  = lg2a(baA);               float lB  = lg2a(baB);
    float PA  = ex2a(kA * lA);           float PB  = ex2a(kB * lB);

    float pdA = ex2a(-P_.w12 * lg2a(dA));
    float pdB = ex2a(-P_.w12 * lg2a(dB));

    float feA = 1.0f;
    feA = (rA == 2.0f) ? P_.w15 : feA;
    feA = (rA == 4.0f) ? P_.w16 : feA;
    float feB = 1.0f;
    feB = (rB == 2.0f) ? P_.w15 : feB;
    feB = (rB == 4.0f) ? P_.w16 : feB;

    float CA = (P_.ew8 * (11.0f - dA)) * feA;
    float CB = (P_.ew8 * (11.0f - dB)) * feB;

    float nsA_s = fmaf(sA, (CA * PA) * (EA - 1.0f), sA);
    float nsB_s = fmaf(sB, (CB * PB) * (EB - 1.0f), sB);
    float nsA_f = fminf((P_.w11 * pdA) * ((PA - 1.0f) * EA), sA);
    float nsB_f = fminf((P_.w11 * pdB) * ((PB - 1.0f) * EB), sB);
    float nsA = suA ? nsA_s : nsA_f;   float nsB = suB ? nsB_s : nsB_f;

    float ndA = fmaf(-P_.w6, rA - 3.0f, dA);
    float ndB = fmaf(-P_.w6, rB - 3.0f, dB);
    ndA = fmaf(P_.c_d2, ndA, P_.c_d1);
    ndB = fmaf(P_.c_d2, ndB, P_.c_d1);

    dA = fminf(10.0f, fmaxf(1.0f, ndA));
    dB = fminf(10.0f, fmaxf(1.0f, ndB));
    sA = fminf(36500.0f, fmaxf(0.01f, nsA));
    sB = fminf(36500.0f, fmaxf(0.01f, nsB));
}

__device__ __forceinline__ void first_lane(float rating, float w0, float w1,
                                           float w2, float w3, float w4, float w5,
                                           float& s, float& d)
{
    int ridx = (int)rating - 1;
    ridx = max(0, min(3, ridx));
    bool valid = (rating >= 1.0f) && (rating <= 4.0f);
    float sv = (ridx == 0) ? w0 : (ridx == 1) ? w1 : (ridx == 2) ? w2 : w3;
    if (!valid) sv = 1.0f;
    d = fminf(10.0f, fmaxf(1.0f, w4 - w5 * (rating - 3.0f)));
    s = fminf(36500.0f, fmaxf(0.01f, sv));
}

__global__ __launch_bounds__(128, 2) void fsrs_kernel(
    const float4* __restrict__ in4,   // (SEQ_LEN, PAIRS) float4 = 2x(t, rating)
    const float*  __restrict__ w,     // (17,)
    float4*       __restrict__ out4,  // (SEQ_LEN, PAIRS) float4 = 2x(s, d) [+ final]
    long long out_elems)
{
    const int i = blockIdx.x * blockDim.x + threadIdx.x;
    if (i >= PAIRS) return;

    const unsigned long long pol = mk_policy();

    const float w0 = w[0], w1 = w[1], w2 = w[2], w3 = w[3];
    const float w4 = w[4], w5 = w[5], w7 = w[7], w8 = w[8], w10 = w[10], w14 = w[14];

    const float LOG2E = 1.4426950408889634f;
    W P_;
    P_.w6 = w[6];  P_.w9 = w[9];  P_.w11 = w[11]; P_.w12 = w[12];
    P_.w13 = w[13]; P_.w15 = w[15]; P_.w16 = w[16];
    P_.ew8  = ex2a(w8 * LOG2E);
    P_.w10l = w10 * LOG2E;
    P_.w14l = w14 * LOG2E;
    P_.c_d1 = w7 * w4;
    P_.c_d2 = 1.0f - w7;

    // ---- first step (step 0), both lanes ----
    float4 x0 = ldg_el4(&in4[i], pol);
    float sA, dA, sB, dB;
    first_lane(x0.y, w0, w1, w2, w3, w4, w5, sA, dA);
    first_lane(x0.w, w0, w1, w2, w3, w4, w5, sB, dB);
    __stcs(&out4[i], make_float4(sA, dA, sB, dB));

    // ---- software-pipelined scan: prefetch distance 16 (two groups) ----
    float4 bufA[8], bufB[8];
    #pragma unroll
    for (int k = 0; k < 8; ++k) bufA[k] = ldg_el4(&in4[(1 + k) * PAIRS + i], pol);
    #pragma unroll
    for (int k = 0; k < 8; ++k) bufB[k] = ldg_el4(&in4[(9 + k) * PAIRS + i], pol);

    // main loop: g = 1,17,33,49,65,81 — all prefetch indices in range, no clamps
    for (int g = 1; g <= 81; g += 16) {
        float4 nA[8], nB[8];
        #pragma unroll
        for (int k = 0; k < 8; ++k)
            nA[k] = ldg_el4(&in4[(g + 16 + k) * PAIRS + i], pol);
        #pragma unroll
        for (int k = 0; k < 8; ++k) {
            step2(bufA[k], sA, dA, sB, dB, P_);
            __stcs(&out4[(g + k) * PAIRS + i], make_float4(sA, dA, sB, dB));
        }
        #pragma unroll
        for (int k = 0; k < 8; ++k) bufA[k] = nA[k];

        #pragma unroll
        for (int k = 0; k < 8; ++k)
            nB[k] = ldg_el4(&in4[(g + 24 + k) * PAIRS + i], pol);
        #pragma unroll
        for (int k = 0; k < 8; ++k) {
            step2(bufB[k], sA, dA, sB, dB, P_);
            __stcs(&out4[(g + 8 + k) * PAIRS + i], make_float4(sA, dA, sB, dB));
        }
        #pragma unroll
        for (int k = 0; k < 8; ++k) bufB[k] = nB[k];
    }

    // peeled iteration g = 97: prefetch steps 113..120 and 121..127 (clamped once)
    {
        float4 nA[8], nB[8];
        #pragma unroll
        for (int k = 0; k < 8; ++k)
            nA[k] = ldg_el4(&in4[(113 + k) * PAIRS + i], pol);
        #pragma unroll
        for (int k = 0; k < 8; ++k) {
            step2(bufA[k], sA, dA, sB, dB, P_);            // steps 97..104
            __stcs(&out4[(97 + k) * PAIRS + i], make_float4(sA, dA, sB, dB));
        }
        #pragma unroll
        for (int k = 0; k < 8; ++k) bufA[k] = nA[k];

        #pragma unroll
        for (int k = 0; k < 8; ++k)
            nB[k] = ldg_el4(&in4[min(121 + k, SEQ_LEN - 1) * PAIRS + i], pol);
        #pragma unroll
        for (int k = 0; k < 8; ++k) {
            step2(bufB[k], sA, dA, sB, dB, P_);            // steps 105..112
            __stcs(&out4[(105 + k) * PAIRS + i], make_float4(sA, dA, sB, dB));
        }
        #pragma unroll
        for (int k = 0; k < 8; ++k) bufB[k] = nB[k];
    }

    // tail: steps 113..120 from bufA, 121..127 from bufB
    #pragma unroll
    for (int k = 0; k < 8; ++k) {
        step2(bufA[k], sA, dA, sB, dB, P_);
        __stcs(&out4[(113 + k) * PAIRS + i], make_float4(sA, dA, sB, dB));
    }
    #pragma unroll
    for (int k = 0; k < 7; ++k) {
        step2(bufB[k], sA, dA, sB, dB, P_);
        __stcs(&out4[(121 + k) * PAIRS + i], make_float4(sA, dA, sB, dB));
    }

    // ---- final_state tensor, if present in the output buffer ----
    if (out_elems >= (long long)(SEQ_LEN + 1) * BATCH * 2) {
        __stcs(&out4[SEQ_LEN * PAIRS + i], make_float4(sA, dA, sB, dB));
    }
}

extern "C" void kernel_launch(void* const* d_in, const int* in_sizes, int n_in,
                              void* d_out, int out_size)
{
    const float4* inputs = (const float4*)d_in[0];  // (128, 65536, 2) f32
    const float*  w      = (const float*)d_in[1];   // (17,) f32
    float4* out          = (float4*)d_out;

    dim3 block(128);
    dim3 grid(PAIRS / 128);                          // 256 blocks
    fsrs_kernel<<<grid, block>>>(inputs, w, out, (long long)out_size);
}

// round 16
// speedup vs baseline: 1.0667x; 1.0667x over previous
#include <cuda_runtime.h>

static constexpr int SEQ_LEN = 128;
static constexpr int BATCH   = 65536;

__device__ __forceinline__ float ex2a(float x) {
    float r; asm("ex2.approx.ftz.f32 %0, %1;" : "=f"(r) : "f"(x)); return r;
}
__device__ __forceinline__ float lg2a(float x) {
    float r; asm("lg2.approx.ftz.f32 %0, %1;" : "=f"(r) : "f"(x)); return r;
}
__device__ __forceinline__ float rcpa(float x) {
    float r; asm("rcp.approx.ftz.f32 %0, %1;" : "=f"(r) : "f"(x)); return r;
}

// policy created once per thread, reused by every load
__device__ __forceinline__ unsigned long long mk_policy() {
    unsigned long long pol;
    asm("createpolicy.fractional.L2::evict_last.b64 %0, 1.0;" : "=l"(pol));
    return pol;
}
__device__ __forceinline__ float2 ldg_el(const float2* p, unsigned long long pol) {
    float2 v;
    asm volatile("ld.global.nc.L2::cache_hint.v2.f32 {%0,%1}, [%2], %3;"
                 : "=f"(v.x), "=f"(v.y) : "l"(p), "l"(pol));
    return v;
}

struct W {
    float w6, w9, w11, w12, w13, w15, w16;
    float ew8, w10l, w14l, c_d1, c_d2;
};

__device__ __forceinline__ void step(float2 x, float& s, float& d, const W& P_)
{
    float t  = x.x;
    float rt = x.y;
    bool succ = (rt > 1.0f);

    // omr = 1 - r = t / (9s + t)
    float denom = fmaf(9.0f, s, t);
    float omr   = t * rcpa(denom);

    // shared EX2: exp((1-r)*w10) | exp((1-r)*w14)
    float cexp = succ ? P_.w10l : P_.w14l;
    float E    = ex2a(omr * cexp);

    // shared pow: s^(-w9) | (s+1)^(w13)
    float base = succ ? s : (s + 1.0f);
    float kpow = succ ? -P_.w9 : P_.w13;
    float P    = ex2a(kpow * lg2a(base));

    // failure-only pow of d — unconditional, off the s-critical path
    float pd   = ex2a(-P_.w12 * lg2a(d));

    float hp  = (rt == 2.0f) ? P_.w15 : 1.0f;
    float eb  = (rt == 4.0f) ? P_.w16 : 1.0f;
    float C   = (P_.ew8 * (11.0f - d)) * (hp * eb);
    float CP  = C * P;

    float ns_succ = fmaf(s, CP * (E - 1.0f), s);
    float ns_fail = fminf((P_.w11 * pd) * ((P - 1.0f) * E), s);
    float ns = succ ? ns_succ : ns_fail;

    float nd = fmaf(-P_.w6, rt - 3.0f, d);
    nd = fmaf(P_.c_d2, nd, P_.c_d1);
    d  = fminf(10.0f, fmaxf(1.0f, nd));
    s  = fminf(36500.0f, fmaxf(0.01f, ns));
}

__global__ __launch_bounds__(128, 4) void fsrs_kernel(
    const float2* __restrict__ in2,   // (SEQ_LEN, BATCH) of (t, rating)
    const float*  __restrict__ w,     // (17,)
    float2*       __restrict__ out2,  // (SEQ_LEN, BATCH) of (s, d) [+ final]
    long long out_elems)
{
    const int b = blockIdx.x * blockDim.x + threadIdx.x;
    if (b >= BATCH) return;

    const unsigned long long pol = mk_policy();

    const float w0 = w[0], w1 = w[1], w2 = w[2], w3 = w[3];
    const float w4 = w[4], w5 = w[5], w7 = w[7], w8 = w[8], w10 = w[10], w14 = w[14];

    const float LOG2E = 1.4426950408889634f;
    W P_;
    P_.w6 = w[6];  P_.w9 = w[9];  P_.w11 = w[11]; P_.w12 = w[12];
    P_.w13 = w[13]; P_.w15 = w[15]; P_.w16 = w[16];
    P_.ew8  = ex2a(w8 * LOG2E);
    P_.w10l = w10 * LOG2E;
    P_.w14l = w14 * LOG2E;
    P_.c_d1 = w7 * w4;
    P_.c_d2 = 1.0f - w7;

    // ---- first step (step 0) ----
    float2 x0 = ldg_el(&in2[b], pol);
    float rating0 = x0.y;
    int ridx = (int)rating0 - 1;
    ridx = max(0, min(3, ridx));
    bool valid = (rating0 >= 1.0f) && (rating0 <= 4.0f);
    float s = (ridx == 0) ? w0 : (ridx == 1) ? w1 : (ridx == 2) ? w2 : w3;
    if (!valid) s = 1.0f;
    float d = fminf(10.0f, fmaxf(1.0f, w4 - w5 * (rating0 - 3.0f)));
    s = fminf(36500.0f, fmaxf(0.01f, s));
    __stcs(&out2[b], make_float2(s, d));

    // ---- software-pipelined scan: prefetch distance 16 (two groups) ----
    float2 bufA[8], bufB[8];
    #pragma unroll
    for (int k = 0; k < 8; ++k) bufA[k] = ldg_el(&in2[(1 + k) * BATCH + b], pol);
    #pragma unroll
    for (int k = 0; k < 8; ++k) bufB[k] = ldg_el(&in2[(9 + k) * BATCH + b], pol);

    // main loop: g = 1,17,33,49,65,81 — all prefetch indices in range, no clamps
    for (int g = 1; g <= 81; g += 16) {
        float2 nA[8], nB[8];
        #pragma unroll
        for (int k = 0; k < 8; ++k)
            nA[k] = ldg_el(&in2[(g + 16 + k) * BATCH + b], pol);
        #pragma unroll
        for (int k = 0; k < 8; ++k) {
            step(bufA[k], s, d, P_);
            __stcs(&out2[(g + k) * BATCH + b], make_float2(s, d));
        }
        #pragma unroll
        for (int k = 0; k < 8; ++k) bufA[k] = nA[k];

        #pragma unroll
        for (int k = 0; k < 8; ++k)
            nB[k] = ldg_el(&in2[(g + 24 + k) * BATCH + b], pol);
        #pragma unroll
        for (int k = 0; k < 8; ++k) {
            step(bufB[k], s, d, P_);
            __stcs(&out2[(g + 8 + k) * BATCH + b], make_float2(s, d));
        }
        #pragma unroll
        for (int k = 0; k < 8; ++k) bufB[k] = nB[k];
    }

    // peeled iteration g = 97: prefetch steps 113..120 and 121..127 (clamped once)
    {
        float2 nA[8], nB[8];
        #pragma unroll
        for (int k = 0; k < 8; ++k)
            nA[k] = ldg_el(&in2[(113 + k) * BATCH + b], pol);
        #pragma unroll
        for (int k = 0; k < 8; ++k) {
            step(bufA[k], s, d, P_);                       // steps 97..104
            __stcs(&out2[(97 + k) * BATCH + b], make_float2(s, d));
        }
        #pragma unroll
        for (int k = 0; k < 8; ++k) bufA[k] = nA[k];

        #pragma unroll
        for (int k = 0; k < 8; ++k)
            nB[k] = ldg_el(&in2[min(121 + k, SEQ_LEN - 1) * BATCH + b], pol);
        #pragma unroll
        for (int k = 0; k < 8; ++k) {
            step(bufB[k], s, d, P_);                       // steps 105..112
            __stcs(&out2[(105 + k) * BATCH + b], make_float2(s, d));
        }
        #pragma unroll
        for (int k = 0; k < 8; ++k) bufB[k] = nB[k];
    }

    // tail: steps 113..120 from bufA, 121..127 from bufB
    #pragma unroll
    for (int k = 0; k < 8; ++k) {
        step(bufA[k], s, d, P_);
        __stcs(&out2[(113 + k) * BATCH + b], make_float2(s, d));
    }
    #pragma unroll
    for (int k = 0; k < 7; ++k) {
        step(bufB[k], s, d, P_);
        __stcs(&out2[(121 + k) * BATCH + b], make_float2(s, d));
    }

    // ---- final_state tensor, if present in the output buffer ----
    if (out_elems >= (long long)(SEQ_LEN + 1) * BATCH * 2) {
        __stcs(&out2[SEQ_LEN * BATCH + b], make_float2(s, d));
    }
}

extern "C" void kernel_launch(void* const* d_in, const int* in_sizes, int n_in,
                              void* d_out, int out_size)
{
    const float2* inputs = (const float2*)d_in[0];  // (128, 65536, 2) f32
    const float*  w      = (const float*)d_in[1];   // (17,) f32
    float2* out          = (float2*)d_out;

    dim3 block(128);
    dim3 grid(BATCH / 128);                          // 512 blocks
    fsrs_kernel<<<grid, block>>>(inputs, w, out, (long long)out_size);
}

// round 17
// speedup vs baseline: 1.1633x; 1.0906x over previous
#include <cuda_runtime.h>

static constexpr int SEQ_LEN = 128;
static constexpr int BATCH   = 65536;

__device__ __forceinline__ float ex2a(float x) {
    float r; asm("ex2.approx.ftz.f32 %0, %1;" : "=f"(r) : "f"(x)); return r;
}
__device__ __forceinline__ float lg2a(float x) {
    float r; asm("lg2.approx.ftz.f32 %0, %1;" : "=f"(r) : "f"(x)); return r;
}
__device__ __forceinline__ float rcpa(float x) {
    float r; asm("rcp.approx.ftz.f32 %0, %1;" : "=f"(r) : "f"(x)); return r;
}

__device__ __forceinline__ unsigned long long mk_policy() {
    unsigned long long pol;
    asm("createpolicy.fractional.L2::evict_last.b64 %0, 1.0;" : "=l"(pol));
    return pol;
}
__device__ __forceinline__ float2 ldg_el(const float2* p, unsigned long long pol) {
    float2 v;
    asm volatile("ld.global.nc.L2::cache_hint.v2.f32 {%0,%1}, [%2], %3;"
                 : "=f"(v.x), "=f"(v.y) : "l"(p), "l"(pol));
    return v;
}

struct W {
    float w6, w9, w11, w12, w13, w15, w16;
    float ew8, w10l, w14l, c_d1, c_d2;
};

// Exponent-fused step: both branches reduce to diff = ex2(e1) - ex2(e2).
//   success: diff = P*E - P      (exponents kpow*L + a      | kpow*L)
//   failure: diff = pd*P*E - pd*E (exponents kpow*L + a + wM | a + wM)
// 5 MUFU/step (rcp, lg2 L, lg2 M, ex2 e1, ex2 e2) instead of 6, and the
// downstream multiply trees collapse into one shared subtract.
__device__ __forceinline__ void step(float2 x, float& s, float& d, const W& P_)
{
    float t  = x.x;
    float rt = x.y;
    bool succ = (rt > 1.0f);

    // a = (1-r)*w = t/(9s+t) * cexp, with t*cexp overlapping the rcp latency
    float denom = fmaf(9.0f, s, t);
    float rc    = rcpa(denom);
    float cexp  = succ ? P_.w10l : P_.w14l;
    float a     = (t * cexp) * rc;

    // shared logs (lg2(d) only matters on failure, computed unconditionally)
    float base = succ ? s : (s + 1.0f);
    float L    = lg2a(base);
    float M    = lg2a(d);

    float kpow = succ ? -P_.w9 : P_.w13;
    float kL   = kpow * L;
    float wM   = -P_.w12 * M;

    float e  = kL + a;
    float e1 = succ ? e  : (e + wM);
    float e2 = succ ? kL : (a + wM);

    float diff = ex2a(e1) - ex2a(e2);

    // success coefficient (off the critical path)
    float fe = 1.0f;
    fe = (rt == 2.0f) ? P_.w15 : fe;
    fe = (rt == 4.0f) ? P_.w16 : fe;
    float sC = s * ((P_.ew8 * (11.0f - d)) * fe);

    float ns_succ = fmaf(sC, diff, s);
    float ns_fail = fminf(P_.w11 * diff, s);
    float ns = succ ? ns_succ : ns_fail;

    float nd = fmaf(-P_.w6, rt - 3.0f, d);
    nd = fmaf(P_.c_d2, nd, P_.c_d1);
    d  = fminf(10.0f, fmaxf(1.0f, nd));
    s  = fminf(36500.0f, fmaxf(0.01f, ns));
}

__global__ __launch_bounds__(128, 4) void fsrs_kernel(
    const float2* __restrict__ in2,   // (SEQ_LEN, BATCH) of (t, rating)
    const float*  __restrict__ w,     // (17,)
    float2*       __restrict__ out2,  // (SEQ_LEN, BATCH) of (s, d) [+ final]
    long long out_elems)
{
    const int b = blockIdx.x * blockDim.x + threadIdx.x;
    if (b >= BATCH) return;

    const unsigned long long pol = mk_policy();

    const float w0 = w[0], w1 = w[1], w2 = w[2], w3 = w[3];
    const float w4 = w[4], w5 = w[5], w7 = w[7], w8 = w[8], w10 = w[10], w14 = w[14];

    const float LOG2E = 1.4426950408889634f;
    W P_;
    P_.w6 = w[6];  P_.w9 = w[9];  P_.w11 = w[11]; P_.w12 = w[12];
    P_.w13 = w[13]; P_.w15 = w[15]; P_.w16 = w[16];
    P_.ew8  = ex2a(w8 * LOG2E);
    P_.w10l = w10 * LOG2E;
    P_.w14l = w14 * LOG2E;
    P_.c_d1 = w7 * w4;
    P_.c_d2 = 1.0f - w7;

    // ---- first step (step 0) ----
    float2 x0 = ldg_el(&in2[b], pol);
    float rating0 = x0.y;
    int ridx = (int)rating0 - 1;
    ridx = max(0, min(3, ridx));
    bool valid = (rating0 >= 1.0f) && (rating0 <= 4.0f);
    float s = (ridx == 0) ? w0 : (ridx == 1) ? w1 : (ridx == 2) ? w2 : w3;
    if (!valid) s = 1.0f;
    float d = fminf(10.0f, fmaxf(1.0f, w4 - w5 * (rating0 - 3.0f)));
    s = fminf(36500.0f, fmaxf(0.01f, s));
    __stcs(&out2[b], make_float2(s, d));

    // ---- software-pipelined scan: prefetch distance 16 (two groups) ----
    float2 bufA[8], bufB[8];
    #pragma unroll
    for (int k = 0; k < 8; ++k) bufA[k] = ldg_el(&in2[(1 + k) * BATCH + b], pol);
    #pragma unroll
    for (int k = 0; k < 8; ++k) bufB[k] = ldg_el(&in2[(9 + k) * BATCH + b], pol);

    // main loop: g = 1,17,33,49,65,81 — all prefetch indices in range, no clamps
    for (int g = 1; g <= 81; g += 16) {
        float2 nA[8], nB[8];
        #pragma unroll
        for (int k = 0; k < 8; ++k)
            nA[k] = ldg_el(&in2[(g + 16 + k) * BATCH + b], pol);
        #pragma unroll
        for (int k = 0; k < 8; ++k) {
            step(bufA[k], s, d, P_);
            __stcs(&out2[(g + k) * BATCH + b], make_float2(s, d));
        }
        #pragma unroll
        for (int k = 0; k < 8; ++k) bufA[k] = nA[k];

        #pragma unroll
        for (int k = 0; k < 8; ++k)
            nB[k] = ldg_el(&in2[(g + 24 + k) * BATCH + b], pol);
        #pragma unroll
        for (int k = 0; k < 8; ++k) {
            step(bufB[k], s, d, P_);
            __stcs(&out2[(g + 8 + k) * BATCH + b], make_float2(s, d));
        }
        #pragma unroll
        for (int k = 0; k < 8; ++k) bufB[k] = nB[k];
    }

    // peeled iteration g = 97: prefetch steps 113..120 and 121..127 (clamped once)
    {
        float2 nA[8], nB[8];
        #pragma unroll
        for (int k = 0; k < 8; ++k)
            nA[k] = ldg_el(&in2[(113 + k) * BATCH + b], pol);
        #pragma unroll
        for (int k = 0; k < 8; ++k) {
            step(bufA[k], s, d, P_);                       // steps 97..104
            __stcs(&out2[(97 + k) * BATCH + b], make_float2(s, d));
        }
        #pragma unroll
        for (int k = 0; k < 8; ++k) bufA[k] = nA[k];

        #pragma unroll
        for (int k = 0; k < 8; ++k)
            nB[k] = ldg_el(&in2[min(121 + k, SEQ_LEN - 1) * BATCH + b], pol);
        #pragma unroll
        for (int k = 0; k < 8; ++k) {
            step(bufB[k], s, d, P_);                       // steps 105..112
            __stcs(&out2[(105 + k) * BATCH + b], make_float2(s, d));
        }
        #pragma unroll
        for (int k = 0; k < 8; ++k) bufB[k] = nB[k];
    }

    // tail: steps 113..120 from bufA, 121..127 from bufB
    #pragma unroll
    for (int k = 0; k < 8; ++k) {
        step(bufA[k], s, d, P_);
        __stcs(&out2[(113 + k) * BATCH + b], make_float2(s, d));
    }
    #pragma unroll
    for (int k = 0; k < 7; ++k) {
        step(bufB[k], s, d, P_);
        __stcs(&out2[(121 + k) * BATCH + b], make_float2(s, d));
    }

    // ---- final_state tensor, if present in the output buffer ----
    if (out_elems >= (long long)(SEQ_LEN + 1) * BATCH * 2) {
        __stcs(&out2[SEQ_LEN * BATCH + b], make_float2(s, d));
    }
}

extern "C" void kernel_launch(void* const* d_in, const int* in_sizes, int n_in,
                              void* d_out, int out_size)
{
    const float2* inputs = (const float2*)d_in[0];  // (128, 65536, 2) f32
    const float*  w      = (const float*)d_in[1];   // (17,) f32
    float2* out          = (float2*)d_out;

    dim3 block(128);
    dim3 grid(BATCH / 128);                          // 512 blocks
    fsrs_kernel<<<grid, block>>>(inputs, w, out, (long long)out_size);
}